// round 14
// baseline (speedup 1.0000x reference)
#include <cuda_runtime.h>
#include <cuda_fp16.h>
#include <math.h>
#include <stdint.h>

#define D_MODEL 1024
#define D_FF    3072
#define NH      16
#define DH      64
#define SEQ     2048
#define BATCH   2
#define ROWS    (BATCH*SEQ)   // 4096
#define WINDOW  128

// ---------------- scratch ----------------
__device__ float  g_x2 [ROWS * D_MODEL];
__device__ __half g_qkvh[ROWS * 3 * D_MODEL];
__device__ __half g_h  [ROWS * D_MODEL];
__device__ __half g_ctx[ROWS * D_MODEL];
__device__ __half g_ff [ROWS * D_FF];

#define WT_TOTAL 10485760
__device__ __half g_w[WT_TOTAL];

// ---------------- PTX helpers ----------------
__device__ __forceinline__ uint32_t smem_u32(const void* p) {
    uint32_t a;
    asm("{ .reg .u64 t; cvta.to.shared.u64 t, %1; cvt.u32.u64 %0, t; }" : "=r"(a) : "l"(p));
    return a;
}
#define CP16(dst, src) \
    asm volatile("cp.async.cg.shared.global [%0], [%1], 16;" :: "r"(dst), "l"(src) : "memory")
#define CP_COMMIT() asm volatile("cp.async.commit_group;" ::: "memory")
#define CP_WAIT2()  asm volatile("cp.async.wait_group 2;" ::: "memory")

#define LDSM4(R, a) \
    asm volatile("ldmatrix.sync.aligned.m8n8.x4.shared.b16 {%0,%1,%2,%3}, [%4];" \
        : "=r"((R)[0]), "=r"((R)[1]), "=r"((R)[2]), "=r"((R)[3]) : "r"(a))
#define LDSM4T(R, a) \
    asm volatile("ldmatrix.sync.aligned.m8n8.x4.trans.shared.b16 {%0,%1,%2,%3}, [%4];" \
        : "=r"((R)[0]), "=r"((R)[1]), "=r"((R)[2]), "=r"((R)[3]) : "r"(a))

#define MMA_F16(d, a, b) \
    asm volatile("mma.sync.aligned.m16n8k16.row.col.f32.f16.f16.f32 " \
        "{%0,%1,%2,%3}, {%4,%5,%6,%7}, {%8,%9}, {%0,%1,%2,%3};" \
        : "+f"((d)[0]), "+f"((d)[1]), "+f"((d)[2]), "+f"((d)[3]) \
        : "r"((a)[0]), "r"((a)[1]), "r"((a)[2]), "r"((a)[3]), \
          "r"((b)[0]), "r"((b)[1]))

// fp16-accumulate variant: d is 2 regs (half2 x2)
#define MMA_F16H(d0, d1, a, b0, b1) \
    asm volatile("mma.sync.aligned.m16n8k16.row.col.f16.f16.f16.f16 " \
        "{%0,%1}, {%2,%3,%4,%5}, {%6,%7}, {%0,%1};" \
        : "+r"(d0), "+r"(d1) \
        : "r"((a)[0]), "r"((a)[1]), "r"((a)[2]), "r"((a)[3]), \
          "r"(b0), "r"(b1))

__device__ __forceinline__ float gelu_exact(float v) {
    return 0.5f * v * (1.0f + erff(v * 0.70710678118654752f));
}

// ---------------- merged weight prep: 4 matrices in one launch ----------------
// tiles per matrix (32x32): qkv 3072, out 1024, ff1 3072, ff2 3072; cum 10240
__global__ void prep_all(const float* __restrict__ W0, const float* __restrict__ W1,
                         const float* __restrict__ W2, const float* __restrict__ W3,
                         __half* __restrict__ Wt) {
    int id = blockIdx.x;
    const float* W; __half* dst; int K, N, local;
    if (id < 3072)      { W = W0; dst = Wt;           K = 1024; N = 3072; local = id; }
    else if (id < 4096) { W = W1; dst = Wt + 3145728; K = 1024; N = 1024; local = id - 3072; }
    else if (id < 7168) { W = W2; dst = Wt + 4194304; K = 1024; N = 3072; local = id - 4096; }
    else                { W = W3; dst = Wt + 7340032; K = 3072; N = 1024; local = id - 7168; }
    int ntx = N >> 5;
    int n0 = (local % ntx) * 32, k0 = (local / ntx) * 32;

    __shared__ float t[32][33];
    int tid = threadIdx.x;
    #pragma unroll
    for (int i = 0; i < 4; i++) {
        int lin = tid + 256 * i;
        int r = lin >> 5, c = lin & 31;
        t[r][c] = W[(size_t)(k0 + r) * N + n0 + c];
    }
    __syncthreads();
    #pragma unroll
    for (int i = 0; i < 4; i++) {
        int lin = tid + 256 * i;
        int n = lin >> 5, k = lin & 31;
        dst[(size_t)(n0 + n) * K + k0 + k] = __float2half_rn(t[k][n]);
    }
}

// ---------------- LayerNorm -> fp16 ----------------
__global__ void ln_half(const float* __restrict__ x, const float* __restrict__ g,
                        const float* __restrict__ bb, __half* __restrict__ oh) {
    int row = blockIdx.x;
    const float* xr = x + (size_t)row * D_MODEL;
    int tid = threadIdx.x;
    float4 v = ((const float4*)xr)[tid];
    float s  = v.x + v.y + v.z + v.w;
    float s2 = v.x*v.x + v.y*v.y + v.z*v.z + v.w*v.w;
    __shared__ float rs[8], rs2[8];
    #pragma unroll
    for (int o = 16; o > 0; o >>= 1) {
        s  += __shfl_xor_sync(0xffffffffu, s,  o);
        s2 += __shfl_xor_sync(0xffffffffu, s2, o);
    }
    int w = tid >> 5, l = tid & 31;
    if (l == 0) { rs[w] = s; rs2[w] = s2; }
    __syncthreads();
    float ts = 0.f, ts2 = 0.f;
    #pragma unroll
    for (int i = 0; i < 8; i++) { ts += rs[i]; ts2 += rs2[i]; }
    float mu  = ts * (1.0f / D_MODEL);
    float var = ts2 * (1.0f / D_MODEL) - mu * mu;
    float inv = rsqrtf(var + 1e-5f);
    float4 gg = ((const float4*)g)[tid];
    float4 bv = ((const float4*)bb)[tid];
    float o0 = (v.x - mu) * inv * gg.x + bv.x;
    float o1 = (v.y - mu) * inv * gg.y + bv.y;
    float o2 = (v.z - mu) * inv * gg.z + bv.z;
    float o3 = (v.w - mu) * inv * gg.w + bv.w;
    size_t base = (size_t)row * D_MODEL + tid * 4;
    *(__half2*)&oh[base]     = __floats2half2_rn(o0, o1);
    *(__half2*)&oh[base + 2] = __floats2half2_rn(o2, o3);
}

// ---------------- fp16 GEMM, fp16-acc inner / fp32 master ----------------
#define ST_STRIDE 20480u
#define GEMM_SMEM (4 * 20480)

template<int EPI>  // 0: Cf=acc+bias  1: +res  2: Ch=half(gelu(acc+bias))  3: Ch=half(acc+bias)
__global__ void __launch_bounds__(256, 2) gemm_mma(
    const __half* __restrict__ A, const __half* __restrict__ B,
    const float* __restrict__ bias, const float* __restrict__ res,
    float* __restrict__ Cf, __half* __restrict__ Ch,
    int M, int N, int K)
{
    extern __shared__ __align__(16) __half smg[];
    uint32_t sbase = smem_u32(smg);
    int tid = threadIdx.x, wid = tid >> 5, lane = tid & 31;
    int g = lane >> 2, tg = lane & 3;
    int wm = wid >> 1, wn = wid & 1;
    int bm = blockIdx.y * 128, bn = blockIdx.x * 128;
    int ns = K >> 5;

    int lt = lane >> 3;
    int arow_l = (lt & 1) * 8 + (lane & 7);
    int ak_l   = (lt >> 1) * 8;
    int brow_l = (lt >> 1) * 8 + (lane & 7);
    int bk_l   = (lt & 1) * 8;

    int lrow = tid >> 1, lkc = (tid & 1) * 2;
    const __half* gA = A + (size_t)(bm + lrow) * K + lkc * 8;
    const __half* gB = B + (size_t)(bn + lrow) * K + lkc * 8;
    uint32_t sA = (uint32_t)(lrow * 80 + lkc * 16);

    float acc[2][8][4];
    #pragma unroll
    for (int mi = 0; mi < 2; mi++)
        #pragma unroll
        for (int ni = 0; ni < 8; ni++)
            #pragma unroll
            for (int q = 0; q < 4; q++) acc[mi][ni][q] = 0.f;

    #pragma unroll
    for (int p = 0; p < 3; p++) {
        uint32_t so = sbase + (uint32_t)p * ST_STRIDE;
        int k0 = p << 5;
        #pragma unroll
        for (int c = 0; c < 2; c++) {
            CP16(so + sA + c * 16u,          gA + k0 + c * 8);
            CP16(so + 10240u + sA + c * 16u, gB + k0 + c * 8);
        }
        CP_COMMIT();
    }

    for (int s = 0; s < ns; s++) {
        CP_WAIT2();
        __syncthreads();

        uint32_t st = sbase + (uint32_t)(s & 3) * ST_STRIDE;
        // A fragments for both k-halves of the stage
        uint32_t ah[2][2][4];   // [ks][mi]
        #pragma unroll
        for (int ks = 0; ks < 2; ks++)
            #pragma unroll
            for (int mi = 0; mi < 2; mi++) {
                uint32_t ao = st + (uint32_t)((wm * 32 + mi * 16 + arow_l) * 40 + ks * 16 + ak_l) * 2;
                LDSM4(ah[ks][mi], ao);
            }
        #pragma unroll
        for (int nb = 0; nb < 4; nb++) {
            uint32_t rb[2][4];   // [ks]
            #pragma unroll
            for (int ks = 0; ks < 2; ks++) {
                uint32_t bo = st + 10240u +
                    (uint32_t)((wn * 64 + nb * 16 + brow_l) * 40 + ks * 16 + bk_l) * 2;
                LDSM4(rb[ks], bo);
            }
            #pragma unroll
            for (int mi = 0; mi < 2; mi++)
                #pragma unroll
                for (int nn = 0; nn < 2; nn++) {
                    uint32_t h0 = 0, h1 = 0;
                    MMA_F16H(h0, h1, ah[0][mi], rb[0][nn*2], rb[0][nn*2+1]);
                    MMA_F16H(h0, h1, ah[1][mi], rb[1][nn*2], rb[1][nn*2+1]);
                    __half2 v0 = *(__half2*)&h0;
                    __half2 v1 = *(__half2*)&h1;
                    int ni = 2 * nb + nn;
                    acc[mi][ni][0] += __low2float(v0);
                    acc[mi][ni][1] += __high2float(v0);
                    acc[mi][ni][2] += __low2float(v1);
                    acc[mi][ni][3] += __high2float(v1);
                }
        }

        if (s + 3 < ns) {
            uint32_t so = sbase + (uint32_t)((s + 3) & 3) * ST_STRIDE;
            int k0 = (s + 3) << 5;
            #pragma unroll
            for (int c = 0; c < 2; c++) {
                CP16(so + sA + c * 16u,          gA + k0 + c * 8);
                CP16(so + 10240u + sA + c * 16u, gB + k0 + c * 8);
            }
        }
        CP_COMMIT();
    }

    #pragma unroll
    for (int mi = 0; mi < 2; mi++) {
        int r0 = bm + wm * 32 + mi * 16 + g;
        int r1 = r0 + 8;
        #pragma unroll
        for (int ni = 0; ni < 8; ni++) {
            int cn = bn + wn * 64 + ni * 8 + tg * 2;
            float2 bv = *(const float2*)&bias[cn];
            float x0 = acc[mi][ni][0] + bv.x;
            float x1 = acc[mi][ni][1] + bv.y;
            float x2 = acc[mi][ni][2] + bv.x;
            float x3 = acc[mi][ni][3] + bv.y;
            size_t o0 = (size_t)r0 * N + cn;
            size_t o1 = (size_t)r1 * N + cn;
            if (EPI == 1) {
                float2 q0 = *(const float2*)&res[o0];
                float2 q1 = *(const float2*)&res[o1];
                x0 += q0.x; x1 += q0.y; x2 += q1.x; x3 += q1.y;
            }
            if (EPI == 2) {
                x0 = gelu_exact(x0); x1 = gelu_exact(x1);
                x2 = gelu_exact(x2); x3 = gelu_exact(x3);
            }
            if (EPI == 2 || EPI == 3) {
                *(__half2*)&Ch[o0] = __floats2half2_rn(x0, x1);
                *(__half2*)&Ch[o1] = __floats2half2_rn(x2, x3);
            } else {
                float2 s0 = {x0, x1}, s1 = {x2, x3};
                *(float2*)&Cf[o0] = s0;
                *(float2*)&Cf[o1] = s1;
            }
        }
    }
}

// ---------------- tensor-core sliding-window attention (verified R13) ----------------
#define ATT_SMEM 90112

__global__ void __launch_bounds__(256, 2) attn_mma(const __half* __restrict__ qkv,
                                                   __half* __restrict__ ctx) {
    extern __shared__ __align__(16) __half asmem[];
    __shared__ float RM[2][4][16], RS[2][4][16];
    __half* QS = asmem;
    __half* KS = asmem + 4608;
    __half* VS = asmem + 18432;
    __half* PS = asmem + 32256;
    uint32_t qb = smem_u32(QS), kbs = smem_u32(KS), vbs = smem_u32(VS), pbs = smem_u32(PS);

    int tid = threadIdx.x, wid = tid >> 5, lane = tid & 31;
    int g = lane >> 2, tg = lane & 3;
    int wm = wid >> 1, wn = wid & 1;
    int lt = lane >> 3;
    int arow_l = (lt & 1) * 8 + (lane & 7);
    int ak_l   = (lt >> 1) * 8;
    int brow_l = (lt >> 1) * 8 + (lane & 7);
    int bk_l   = (lt & 1) * 8;

    int q0 = blockIdx.x * 64, h = blockIdx.y, b = blockIdx.z;
    int k0 = q0 - WINDOW;
    const __half* base = qkv + (size_t)b * SEQ * (3 * D_MODEL);

    #pragma unroll
    for (int i = 0; i < 2; i++) {
        int idx = tid + 256 * i;
        int r = idx >> 3, c = idx & 7;
        uint4 v = *(const uint4*)(base + (size_t)(q0 + r) * (3 * D_MODEL) + h * DH + c * 8);
        *(uint4*)(QS + r * 72 + c * 8) = v;
    }
    #pragma unroll
    for (int i = 0; i < 6; i++) {
        int idx = tid + 256 * i;
        int r = idx >> 3, c = idx & 7;
        int kj = k0 + r;
        uint4 kv = {0,0,0,0}, vv = {0,0,0,0};
        if (kj >= 0) {
            kv = *(const uint4*)(base + (size_t)kj * (3 * D_MODEL) + D_MODEL + h * DH + c * 8);
            vv = *(const uint4*)(base + (size_t)kj * (3 * D_MODEL) + 2 * D_MODEL + h * DH + c * 8);
        }
        *(uint4*)(KS + r * 72 + c * 8) = kv;
        *(uint4*)(VS + r * 72 + c * 8) = vv;
    }
    __syncthreads();

    uint32_t aq[4][4];
    #pragma unroll
    for (int ks = 0; ks < 4; ks++)
        LDSM4(aq[ks], qb + (uint32_t)((wm * 16 + arow_l) * 72 + ks * 16 + ak_l) * 2);

    float sacc[12][4];
    #pragma unroll
    for (int t = 0; t < 12; t++)
        #pragma unroll
        for (int q = 0; q < 4; q++) sacc[t][q] = 0.f;

    #pragma unroll
    for (int c = 0; c < 6; c++) {
        int kb2 = wn * 96 + c * 16;
        #pragma unroll
        for (int ks = 0; ks < 4; ks++) {
            uint32_t r[4];
            LDSM4(r, kbs + (uint32_t)((kb2 + brow_l) * 72 + ks * 16 + bk_l) * 2);
            uint32_t b0[2] = {r[0], r[1]}, b1[2] = {r[2], r[3]};
            MMA_F16(sacc[2*c],   aq[ks], b0);
            MMA_F16(sacc[2*c+1], aq[ks], b1);
        }
    }

    int r0 = wm * 16 + g, r1 = r0 + 8;
    float m0 = -1e30f, m1 = -1e30f;
    #pragma unroll
    for (int t = 0; t < 12; t++) {
        int j0 = wn * 96 + t * 8 + tg * 2, j1 = j0 + 1;
        bool a00 = (j0 > r0) && (j0 <= r0 + WINDOW) && (k0 + j0 >= 0);
        bool a01 = (j1 > r0) && (j1 <= r0 + WINDOW) && (k0 + j1 >= 0);
        bool a10 = (j0 > r1) && (j0 <= r1 + WINDOW) && (k0 + j0 >= 0);
        bool a11 = (j1 > r1) && (j1 <= r1 + WINDOW) && (k0 + j1 >= 0);
        sacc[t][0] = a00 ? sacc[t][0] * 0.125f : -1e30f;
        sacc[t][1] = a01 ? sacc[t][1] * 0.125f : -1e30f;
        sacc[t][2] = a10 ? sacc[t][2] * 0.125f : -1e30f;
        sacc[t][3] = a11 ? sacc[t][3] * 0.125f : -1e30f;
        m0 = fmaxf(m0, fmaxf(sacc[t][0], sacc[t][1]));
        m1 = fmaxf(m1, fmaxf(sacc[t][2], sacc[t][3]));
    }
    m0 = fmaxf(m0, __shfl_xor_sync(0xffffffffu, m0, 1));
    m0 = fmaxf(m0, __shfl_xor_sync(0xffffffffu, m0, 2));
    m1 = fmaxf(m1, __shfl_xor_sync(0xffffffffu, m1, 1));
    m1 = fmaxf(m1, __shfl_xor_sync(0xffffffffu, m1, 2));
    if (tg == 0) { RM[wn][wm][g] = m0; RM[wn][wm][g + 8] = m1; }
    __syncthreads();
    float gm0 = fmaxf(RM[0][wm][g],     RM[1][wm][g]);
    float gm1 = fmaxf(RM[0][wm][g + 8], RM[1][wm][g + 8]);

    float s0 = 0.f, s1 = 0.f;
    #pragma unroll
    for (int t = 0; t < 12; t++) {
        float p0 = __expf(sacc[t][0] - gm0);
        float p1 = __expf(sacc[t][1] - gm0);
        float p2 = __expf(sacc[t][2] - gm1);
        float p3 = __expf(sacc[t][3] - gm1);
        s0 += p0 + p1; s1 += p2 + p3;
        int col = wn * 96 + t * 8 + tg * 2;
        *(__half2*)(PS + r0 * 200 + col) = __floats2half2_rn(p0, p1);
        *(__half2*)(PS + r1 * 200 + col) = __floats2half2_rn(p2, p3);
    }
    s0 += __shfl_xor_sync(0xffffffffu, s0, 1);
    s0 += __shfl_xor_sync(0xffffffffu, s0, 2);
    s1 += __shfl_xor_sync(0xffffffffu, s1, 1);
    s1 += __shfl_xor_sync(0xffffffffu, s1, 2);
    if (tg == 0) { RS[wn][wm][g] = s0; RS[wn][wm][g + 8] = s1; }
    __syncthreads();

    float oacc[4][4];
    #pragma unroll
    for (int t = 0; t < 4; t++)
        #pragma unroll
        for (int q = 0; q < 4; q++) oacc[t][q] = 0.f;

    #pragma unroll
    for (int kc = 0; kc < 12; kc++) {
        uint32_t pa[4];
        LDSM4(pa, pbs + (uint32_t)((wm * 16 + arow_l) * 200 + kc * 16 + ak_l) * 2);
        #pragma unroll
        for (int nh2 = 0; nh2 < 2; nh2++) {
            uint32_t r[4];
            LDSM4T(r, vbs + (uint32_t)((kc * 16 + arow_l) * 72 + wn * 32 + nh2 * 16 + ak_l) * 2);
            uint32_t b0[2] = {r[0], r[1]}, b1[2] = {r[2], r[3]};
            MMA_F16(oacc[nh2*2],   pa, b0);
            MMA_F16(oacc[nh2*2+1], pa, b1);
        }
    }

    float inv0 = 1.f / (RS[0][wm][g]     + RS[1][wm][g]);
    float inv1 = 1.f / (RS[0][wm][g + 8] + RS[1][wm][g + 8]);
    size_t ro0 = (size_t)(b * SEQ + q0 + r0) * D_MODEL + h * DH;
    size_t ro1 = (size_t)(b * SEQ + q0 + r1) * D_MODEL + h * DH;
    #pragma unroll
    for (int t = 0; t < 4; t++) {
        int col = wn * 32 + t * 8 + tg * 2;
        *(__half2*)(ctx + ro0 + col) = __floats2half2_rn(oacc[t][0] * inv0, oacc[t][1] * inv0);
        *(__half2*)(ctx + ro1 + col) = __floats2half2_rn(oacc[t][2] * inv1, oacc[t][3] * inv1);
    }
}

// ---------------- launcher ----------------
extern "C" void kernel_launch(void* const* d_in, const int* in_sizes, int n_in,
                              void* d_out, int out_size) {
    const float* x     = (const float*)d_in[0];
    const float* w_qkv = (const float*)d_in[1];
    const float* b_qkv = (const float*)d_in[2];
    const float* w_out = (const float*)d_in[3];
    const float* b_out = (const float*)d_in[4];
    const float* w_ff1 = (const float*)d_in[5];
    const float* b_ff1 = (const float*)d_in[6];
    const float* w_ff2 = (const float*)d_in[7];
    const float* b_ff2 = (const float*)d_in[8];
    const float* ln1_g = (const float*)d_in[9];
    const float* ln1_b = (const float*)d_in[10];
    const float* ln2_g = (const float*)d_in[11];
    const float* ln2_b = (const float*)d_in[12];
    float* out = (float*)d_out;

    float *x2;
    __half *qkvh, *h, *ctx, *ff, *w;
    cudaGetSymbolAddress((void**)&x2,   g_x2);
    cudaGetSymbolAddress((void**)&qkvh, g_qkvh);
    cudaGetSymbolAddress((void**)&h,    g_h);
    cudaGetSymbolAddress((void**)&ctx,  g_ctx);
    cudaGetSymbolAddress((void**)&ff,   g_ff);
    cudaGetSymbolAddress((void**)&w,    g_w);

    __half *w_qkv_t = w;
    __half *w_out_t = w + 3145728;
    __half *w_ff1_t = w + 4194304;
    __half *w_ff2_t = w + 7340032;

    cudaFuncSetAttribute(gemm_mma<1>, cudaFuncAttributeMaxDynamicSharedMemorySize, GEMM_SMEM);
    cudaFuncSetAttribute(gemm_mma<2>, cudaFuncAttributeMaxDynamicSharedMemorySize, GEMM_SMEM);
    cudaFuncSetAttribute(gemm_mma<3>, cudaFuncAttributeMaxDynamicSharedMemorySize, GEMM_SMEM);
    cudaFuncSetAttribute(attn_mma, cudaFuncAttributeMaxDynamicSharedMemorySize, ATT_SMEM);

    // 0. weight prep (one merged launch)
    prep_all<<<10240, 256>>>(w_qkv, w_out, w_ff1, w_ff2, w);

    // 1. LN1 -> fp16
    ln_half<<<ROWS, 256>>>(x, ln1_g, ln1_b, h);

    // 2. QKV projection -> fp16
    gemm_mma<3><<<dim3(3 * D_MODEL / 128, ROWS / 128), 256, GEMM_SMEM>>>(
        h, w_qkv_t, b_qkv, nullptr, nullptr, qkvh, ROWS, 3 * D_MODEL, D_MODEL);

    // 3. tensor-core attention -> fp16 ctx
    attn_mma<<<dim3(SEQ / 64, NH, BATCH), 256, ATT_SMEM>>>(qkvh, ctx);

    // 4. out-projection + residual -> fp32 x2
    gemm_mma<1><<<dim3(D_MODEL / 128, ROWS / 128), 256, GEMM_SMEM>>>(
        ctx, w_out_t, b_out, x, x2, nullptr, ROWS, D_MODEL, D_MODEL);

    // 5. LN2 -> fp16
    ln_half<<<ROWS, 256>>>(x2, ln2_g, ln2_b, h);

    // 6. FF1 + gelu -> fp16
    gemm_mma<2><<<dim3(D_FF / 128, ROWS / 128), 256, GEMM_SMEM>>>(
        h, w_ff1_t, b_ff1, nullptr, nullptr, ff, ROWS, D_FF, D_MODEL);

    // 7. FF2 + residual -> output
    gemm_mma<1><<<dim3(D_MODEL / 128, ROWS / 128), 256, GEMM_SMEM>>>(
        ff, w_ff2_t, b_ff2, x2, out, nullptr, ROWS, D_MODEL, D_FF);
}

// round 16
// speedup vs baseline: 1.0820x; 1.0820x over previous
#include <cuda_runtime.h>
#include <cuda_fp16.h>
#include <math.h>
#include <stdint.h>

#define D_MODEL 1024
#define D_FF    3072
#define NH      16
#define DH      64
#define SEQ     2048
#define BATCH   2
#define ROWS    (BATCH*SEQ)   // 4096
#define WINDOW  128
#define NPERS   296           // persistent grid: 148 SMs * 2 CTAs

// ---------------- scratch ----------------
__device__ float  g_x2 [ROWS * D_MODEL];
__device__ __half g_qkvh[ROWS * 3 * D_MODEL];
__device__ __half g_h  [ROWS * D_MODEL];
__device__ __half g_ctx[ROWS * D_MODEL];
__device__ __half g_ff [ROWS * D_FF];

#define WT_TOTAL 10485760
__device__ __half g_w[WT_TOTAL];

// ---------------- PTX helpers ----------------
__device__ __forceinline__ uint32_t smem_u32(const void* p) {
    uint32_t a;
    asm("{ .reg .u64 t; cvta.to.shared.u64 t, %1; cvt.u32.u64 %0, t; }" : "=r"(a) : "l"(p));
    return a;
}
#define CP16(dst, src) \
    asm volatile("cp.async.cg.shared.global [%0], [%1], 16;" :: "r"(dst), "l"(src) : "memory")
#define CP_COMMIT() asm volatile("cp.async.commit_group;" ::: "memory")
#define CP_WAIT2()  asm volatile("cp.async.wait_group 2;" ::: "memory")
#define CP_WAIT0()  asm volatile("cp.async.wait_group 0;" ::: "memory")

#define LDSM4(R, a) \
    asm volatile("ldmatrix.sync.aligned.m8n8.x4.shared.b16 {%0,%1,%2,%3}, [%4];" \
        : "=r"((R)[0]), "=r"((R)[1]), "=r"((R)[2]), "=r"((R)[3]) : "r"(a))
#define LDSM4T(R, a) \
    asm volatile("ldmatrix.sync.aligned.m8n8.x4.trans.shared.b16 {%0,%1,%2,%3}, [%4];" \
        : "=r"((R)[0]), "=r"((R)[1]), "=r"((R)[2]), "=r"((R)[3]) : "r"(a))

#define MMA_F16(d, a, b) \
    asm volatile("mma.sync.aligned.m16n8k16.row.col.f32.f16.f16.f32 " \
        "{%0,%1,%2,%3}, {%4,%5,%6,%7}, {%8,%9}, {%0,%1,%2,%3};" \
        : "+f"((d)[0]), "+f"((d)[1]), "+f"((d)[2]), "+f"((d)[3]) \
        : "r"((a)[0]), "r"((a)[1]), "r"((a)[2]), "r"((a)[3]), \
          "r"((b)[0]), "r"((b)[1]))

__device__ __forceinline__ float gelu_exact(float v) {
    return 0.5f * v * (1.0f + erff(v * 0.70710678118654752f));
}

// ---------------- merged weight prep ----------------
__global__ void prep_all(const float* __restrict__ W0, const float* __restrict__ W1,
                         const float* __restrict__ W2, const float* __restrict__ W3,
                         __half* __restrict__ Wt) {
    int id = blockIdx.x;
    const float* W; __half* dst; int K, N, local;
    if (id < 3072)      { W = W0; dst = Wt;           K = 1024; N = 3072; local = id; }
    else if (id < 4096) { W = W1; dst = Wt + 3145728; K = 1024; N = 1024; local = id - 3072; }
    else if (id < 7168) { W = W2; dst = Wt + 4194304; K = 1024; N = 3072; local = id - 4096; }
    else                { W = W3; dst = Wt + 7340032; K = 3072; N = 1024; local = id - 7168; }
    int ntx = N >> 5;
    int n0 = (local % ntx) * 32, k0 = (local / ntx) * 32;

    __shared__ float t[32][33];
    int tid = threadIdx.x;
    #pragma unroll
    for (int i = 0; i < 4; i++) {
        int lin = tid + 256 * i;
        int r = lin >> 5, c = lin & 31;
        t[r][c] = W[(size_t)(k0 + r) * N + n0 + c];
    }
    __syncthreads();
    #pragma unroll
    for (int i = 0; i < 4; i++) {
        int lin = tid + 256 * i;
        int n = lin >> 5, k = lin & 31;
        dst[(size_t)(n0 + n) * K + k0 + k] = __float2half_rn(t[k][n]);
    }
}

// ---------------- LayerNorm -> fp16 ----------------
__global__ void ln_half(const float* __restrict__ x, const float* __restrict__ g,
                        const float* __restrict__ bb, __half* __restrict__ oh) {
    int row = blockIdx.x;
    const float* xr = x + (size_t)row * D_MODEL;
    int tid = threadIdx.x;
    float4 v = ((const float4*)xr)[tid];
    float s  = v.x + v.y + v.z + v.w;
    float s2 = v.x*v.x + v.y*v.y + v.z*v.z + v.w*v.w;
    __shared__ float rs[8], rs2[8];
    #pragma unroll
    for (int o = 16; o > 0; o >>= 1) {
        s  += __shfl_xor_sync(0xffffffffu, s,  o);
        s2 += __shfl_xor_sync(0xffffffffu, s2, o);
    }
    int w = tid >> 5, l = tid & 31;
    if (l == 0) { rs[w] = s; rs2[w] = s2; }
    __syncthreads();
    float ts = 0.f, ts2 = 0.f;
    #pragma unroll
    for (int i = 0; i < 8; i++) { ts += rs[i]; ts2 += rs2[i]; }
    float mu  = ts * (1.0f / D_MODEL);
    float var = ts2 * (1.0f / D_MODEL) - mu * mu;
    float inv = rsqrtf(var + 1e-5f);
    float4 gg = ((const float4*)g)[tid];
    float4 bv = ((const float4*)bb)[tid];
    float o0 = (v.x - mu) * inv * gg.x + bv.x;
    float o1 = (v.y - mu) * inv * gg.y + bv.y;
    float o2 = (v.z - mu) * inv * gg.z + bv.z;
    float o3 = (v.w - mu) * inv * gg.w + bv.w;
    size_t base = (size_t)row * D_MODEL + tid * 4;
    *(__half2*)&oh[base]     = __floats2half2_rn(o0, o1);
    *(__half2*)&oh[base + 2] = __floats2half2_rn(o2, o3);
}

// ---------------- persistent fp16 pipelined mma GEMM ----------------
#define ST_STRIDE 20480u
#define GEMM_SMEM (4 * 20480)

template<int EPI>  // 0: Cf=acc+bias  1: +res  2: Ch=half(gelu(acc+bias))  3: Ch=half(acc+bias)
__global__ void __launch_bounds__(256, 2) gemm_mma(
    const __half* __restrict__ A, const __half* __restrict__ B,
    const float* __restrict__ bias, const float* __restrict__ res,
    float* __restrict__ Cf, __half* __restrict__ Ch,
    int M, int N, int K)
{
    extern __shared__ __align__(16) __half smg[];
    uint32_t sbase = smem_u32(smg);
    int tid = threadIdx.x, wid = tid >> 5, lane = tid & 31;
    int g = lane >> 2, tg = lane & 3;
    int wm = wid >> 1, wn = wid & 1;
    int ns = K >> 5;
    int ntiles = (M >> 7) * (N >> 7);
    int ntx = N >> 7;

    int lt = lane >> 3;
    int arow_l = (lt & 1) * 8 + (lane & 7);
    int ak_l   = (lt >> 1) * 8;
    int brow_l = (lt >> 1) * 8 + (lane & 7);
    int bk_l   = (lt & 1) * 8;

    int lrow = tid >> 1, lkc = (tid & 1) * 2;
    uint32_t sA = (uint32_t)(lrow * 80 + lkc * 16);

    for (int tile = blockIdx.x; tile < ntiles; tile += NPERS) {
        int bm = (tile / ntx) * 128, bn = (tile % ntx) * 128;
        const __half* gA = A + (size_t)(bm + lrow) * K + lkc * 8;
        const __half* gB = B + (size_t)(bn + lrow) * K + lkc * 8;

        float acc[2][8][4];
        #pragma unroll
        for (int mi = 0; mi < 2; mi++)
            #pragma unroll
            for (int ni = 0; ni < 8; ni++)
                #pragma unroll
                for (int q = 0; q < 4; q++) acc[mi][ni][q] = 0.f;

        #pragma unroll
        for (int p = 0; p < 3; p++) {
            uint32_t so = sbase + (uint32_t)p * ST_STRIDE;
            int k0 = p << 5;
            #pragma unroll
            for (int c = 0; c < 2; c++) {
                CP16(so + sA + c * 16u,          gA + k0 + c * 8);
                CP16(so + 10240u + sA + c * 16u, gB + k0 + c * 8);
            }
            CP_COMMIT();
        }

        for (int s = 0; s < ns; s++) {
            CP_WAIT2();
            __syncthreads();

            uint32_t st = sbase + (uint32_t)(s & 3) * ST_STRIDE;
            #pragma unroll
            for (int ks = 0; ks < 2; ks++) {
                int ks16 = ks * 16;
                uint32_t ah[2][4], bh[8][2];
                #pragma unroll
                for (int mi = 0; mi < 2; mi++) {
                    uint32_t ao = st + (uint32_t)((wm * 32 + mi * 16 + arow_l) * 40 + ks16 + ak_l) * 2;
                    LDSM4(ah[mi], ao);
                }
                #pragma unroll
                for (int nb = 0; nb < 4; nb++) {
                    uint32_t bo = st + 10240u +
                        (uint32_t)((wn * 64 + nb * 16 + brow_l) * 40 + ks16 + bk_l) * 2;
                    uint32_t r[4];
                    LDSM4(r, bo);
                    bh[2*nb][0] = r[0]; bh[2*nb][1] = r[1];
                    bh[2*nb+1][0] = r[2]; bh[2*nb+1][1] = r[3];
                }
                #pragma unroll
                for (int mi = 0; mi < 2; mi++)
                    #pragma unroll
                    for (int ni = 0; ni < 8; ni++)
                        MMA_F16(acc[mi][ni], ah[mi], bh[ni]);
            }

            if (s + 3 < ns) {
                uint32_t so = sbase + (uint32_t)((s + 3) & 3) * ST_STRIDE;
                int k0 = (s + 3) << 5;
                #pragma unroll
                for (int c = 0; c < 2; c++) {
                    CP16(so + sA + c * 16u,          gA + k0 + c * 8);
                    CP16(so + 10240u + sA + c * 16u, gB + k0 + c * 8);
                }
            }
            CP_COMMIT();
        }

        // epilogue for this tile
        #pragma unroll
        for (int mi = 0; mi < 2; mi++) {
            int r0 = bm + wm * 32 + mi * 16 + g;
            int r1 = r0 + 8;
            #pragma unroll
            for (int ni = 0; ni < 8; ni++) {
                int cn = bn + wn * 64 + ni * 8 + tg * 2;
                float2 bv = *(const float2*)&bias[cn];
                float x0 = acc[mi][ni][0] + bv.x;
                float x1 = acc[mi][ni][1] + bv.y;
                float x2 = acc[mi][ni][2] + bv.x;
                float x3 = acc[mi][ni][3] + bv.y;
                size_t o0 = (size_t)r0 * N + cn;
                size_t o1 = (size_t)r1 * N + cn;
                if (EPI == 1) {
                    float2 q0 = *(const float2*)&res[o0];
                    float2 q1 = *(const float2*)&res[o1];
                    x0 += q0.x; x1 += q0.y; x2 += q1.x; x3 += q1.y;
                }
                if (EPI == 2) {
                    x0 = gelu_exact(x0); x1 = gelu_exact(x1);
                    x2 = gelu_exact(x2); x3 = gelu_exact(x3);
                }
                if (EPI == 2 || EPI == 3) {
                    *(__half2*)&Ch[o0] = __floats2half2_rn(x0, x1);
                    *(__half2*)&Ch[o1] = __floats2half2_rn(x2, x3);
                } else {
                    float2 s0 = {x0, x1}, s1 = {x2, x3};
                    *(float2*)&Cf[o0] = s0;
                    *(float2*)&Cf[o1] = s1;
                }
            }
        }

        // drain outstanding groups; slots safe for next tile
        CP_WAIT0();
        __syncthreads();
    }
}

// ---------------- tensor-core sliding-window attention (verified R13) ----------------
#define ATT_SMEM 90112

__global__ void __launch_bounds__(256, 2) attn_mma(const __half* __restrict__ qkv,
                                                   __half* __restrict__ ctx) {
    extern __shared__ __align__(16) __half asmem[];
    __shared__ float RM[2][4][16], RS[2][4][16];
    __half* QS = asmem;
    __half* KS = asmem + 4608;
    __half* VS = asmem + 18432;
    __half* PS = asmem + 32256;
    uint32_t qb = smem_u32(QS), kbs = smem_u32(KS), vbs = smem_u32(VS), pbs = smem_u32(PS);

    int tid = threadIdx.x, wid = tid >> 5, lane = tid & 31;
    int g = lane >> 2, tg = lane & 3;
    int wm = wid >> 1, wn = wid & 1;
    int lt = lane >> 3;
    int arow_l = (lt & 1) * 8 + (lane & 7);
    int ak_l   = (lt >> 1) * 8;
    int brow_l = (lt >> 1) * 8 + (lane & 7);
    int bk_l   = (lt & 1) * 8;

    int q0 = blockIdx.x * 64, h = blockIdx.y, b = blockIdx.z;
    int k0 = q0 - WINDOW;
    const __half* base = qkv + (size_t)b * SEQ * (3 * D_MODEL);

    #pragma unroll
    for (int i = 0; i < 2; i++) {
        int idx = tid + 256 * i;
        int r = idx >> 3, c = idx & 7;
        uint4 v = *(const uint4*)(base + (size_t)(q0 + r) * (3 * D_MODEL) + h * DH + c * 8);
        *(uint4*)(QS + r * 72 + c * 8) = v;
    }
    #pragma unroll
    for (int i = 0; i < 6; i++) {
        int idx = tid + 256 * i;
        int r = idx >> 3, c = idx & 7;
        int kj = k0 + r;
        uint4 kv = {0,0,0,0}, vv = {0,0,0,0};
        if (kj >= 0) {
            kv = *(const uint4*)(base + (size_t)kj * (3 * D_MODEL) + D_MODEL + h * DH + c * 8);
            vv = *(const uint4*)(base + (size_t)kj * (3 * D_MODEL) + 2 * D_MODEL + h * DH + c * 8);
        }
        *(uint4*)(KS + r * 72 + c * 8) = kv;
        *(uint4*)(VS + r * 72 + c * 8) = vv;
    }
    __syncthreads();

    uint32_t aq[4][4];
    #pragma unroll
    for (int ks = 0; ks < 4; ks++)
        LDSM4(aq[ks], qb + (uint32_t)((wm * 16 + arow_l) * 72 + ks * 16 + ak_l) * 2);

    float sacc[12][4];
    #pragma unroll
    for (int t = 0; t < 12; t++)
        #pragma unroll
        for (int q = 0; q < 4; q++) sacc[t][q] = 0.f;

    #pragma unroll
    for (int c = 0; c < 6; c++) {
        int kb2 = wn * 96 + c * 16;
        #pragma unroll
        for (int ks = 0; ks < 4; ks++) {
            uint32_t r[4];
            LDSM4(r, kbs + (uint32_t)((kb2 + brow_l) * 72 + ks * 16 + bk_l) * 2);
            uint32_t b0[2] = {r[0], r[1]}, b1[2] = {r[2], r[3]};
            MMA_F16(sacc[2*c],   aq[ks], b0);
            MMA_F16(sacc[2*c+1], aq[ks], b1);
        }
    }

    int r0 = wm * 16 + g, r1 = r0 + 8;
    float m0 = -1e30f, m1 = -1e30f;
    #pragma unroll
    for (int t = 0; t < 12; t++) {
        int j0 = wn * 96 + t * 8 + tg * 2, j1 = j0 + 1;
        bool a00 = (j0 > r0) && (j0 <= r0 + WINDOW) && (k0 + j0 >= 0);
        bool a01 = (j1 > r0) && (j1 <= r0 + WINDOW) && (k0 + j1 >= 0);
        bool a10 = (j0 > r1) && (j0 <= r1 + WINDOW) && (k0 + j0 >= 0);
        bool a11 = (j1 > r1) && (j1 <= r1 + WINDOW) && (k0 + j1 >= 0);
        sacc[t][0] = a00 ? sacc[t][0] * 0.125f : -1e30f;
        sacc[t][1] = a01 ? sacc[t][1] * 0.125f : -1e30f;
        sacc[t][2] = a10 ? sacc[t][2] * 0.125f : -1e30f;
        sacc[t][3] = a11 ? sacc[t][3] * 0.125f : -1e30f;
        m0 = fmaxf(m0, fmaxf(sacc[t][0], sacc[t][1]));
        m1 = fmaxf(m1, fmaxf(sacc[t][2], sacc[t][3]));
    }
    m0 = fmaxf(m0, __shfl_xor_sync(0xffffffffu, m0, 1));
    m0 = fmaxf(m0, __shfl_xor_sync(0xffffffffu, m0, 2));
    m1 = fmaxf(m1, __shfl_xor_sync(0xffffffffu, m1, 1));
    m1 = fmaxf(m1, __shfl_xor_sync(0xffffffffu, m1, 2));
    if (tg == 0) { RM[wn][wm][g] = m0; RM[wn][wm][g + 8] = m1; }
    __syncthreads();
    float gm0 = fmaxf(RM[0][wm][g],     RM[1][wm][g]);
    float gm1 = fmaxf(RM[0][wm][g + 8], RM[1][wm][g + 8]);

    float s0 = 0.f, s1 = 0.f;
    #pragma unroll
    for (int t = 0; t < 12; t++) {
        float p0 = __expf(sacc[t][0] - gm0);
        float p1 = __expf(sacc[t][1] - gm0);
        float p2 = __expf(sacc[t][2] - gm1);
        float p3 = __expf(sacc[t][3] - gm1);
        s0 += p0 + p1; s1 += p2 + p3;
        int col = wn * 96 + t * 8 + tg * 2;
        *(__half2*)(PS + r0 * 200 + col) = __floats2half2_rn(p0, p1);
        *(__half2*)(PS + r1 * 200 + col) = __floats2half2_rn(p2, p3);
    }
    s0 += __shfl_xor_sync(0xffffffffu, s0, 1);
    s0 += __shfl_xor_sync(0xffffffffu, s0, 2);
    s1 += __shfl_xor_sync(0xffffffffu, s1, 1);
    s1 += __shfl_xor_sync(0xffffffffu, s1, 2);
    if (tg == 0) { RS[wn][wm][g] = s0; RS[wn][wm][g + 8] = s1; }
    __syncthreads();

    float oacc[4][4];
    #pragma unroll
    for (int t = 0; t < 4; t++)
        #pragma unroll
        for (int q = 0; q < 4; q++) oacc[t][q] = 0.f;

    #pragma unroll
    for (int kc = 0; kc < 12; kc++) {
        uint32_t pa[4];
        LDSM4(pa, pbs + (uint32_t)((wm * 16 + arow_l) * 200 + kc * 16 + ak_l) * 2);
        #pragma unroll
        for (int nh2 = 0; nh2 < 2; nh2++) {
            uint32_t r[4];
            LDSM4T(r, vbs + (uint32_t)((kc * 16 + arow_l) * 72 + wn * 32 + nh2 * 16 + ak_l) * 2);
            uint32_t b0[2] = {r[0], r[1]}, b1[2] = {r[2], r[3]};
            MMA_F16(oacc[nh2*2],   pa, b0);
            MMA_F16(oacc[nh2*2+1], pa, b1);
        }
    }

    float inv0 = 1.f / (RS[0][wm][g]     + RS[1][wm][g]);
    float inv1 = 1.f / (RS[0][wm][g + 8] + RS[1][wm][g + 8]);
    size_t ro0 = (size_t)(b * SEQ + q0 + r0) * D_MODEL + h * DH;
    size_t ro1 = (size_t)(b * SEQ + q0 + r1) * D_MODEL + h * DH;
    #pragma unroll
    for (int t = 0; t < 4; t++) {
        int col = wn * 32 + t * 8 + tg * 2;
        *(__half2*)(ctx + ro0 + col) = __floats2half2_rn(oacc[t][0] * inv0, oacc[t][1] * inv0);
        *(__half2*)(ctx + ro1 + col) = __floats2half2_rn(oacc[t][2] * inv1, oacc[t][3] * inv1);
    }
}

// ---------------- launcher ----------------
extern "C" void kernel_launch(void* const* d_in, const int* in_sizes, int n_in,
                              void* d_out, int out_size) {
    const float* x     = (const float*)d_in[0];
    const float* w_qkv = (const float*)d_in[1];
    const float* b_qkv = (const float*)d_in[2];
    const float* w_out = (const float*)d_in[3];
    const float* b_out = (const float*)d_in[4];
    const float* w_ff1 = (const float*)d_in[5];
    const float* b_ff1 = (const float*)d_in[6];
    const float* w_ff2 = (const float*)d_in[7];
    const float* b_ff2 = (const float*)d_in[8];
    const float* ln1_g = (const float*)d_in[9];
    const float* ln1_b = (const float*)d_in[10];
    const float* ln2_g = (const float*)d_in[11];
    const float* ln2_b = (const float*)d_in[12];
    float* out = (float*)d_out;

    float *x2;
    __half *qkvh, *h, *ctx, *ff, *w;
    cudaGetSymbolAddress((void**)&x2,   g_x2);
    cudaGetSymbolAddress((void**)&qkvh, g_qkvh);
    cudaGetSymbolAddress((void**)&h,    g_h);
    cudaGetSymbolAddress((void**)&ctx,  g_ctx);
    cudaGetSymbolAddress((void**)&ff,   g_ff);
    cudaGetSymbolAddress((void**)&w,    g_w);

    __half *w_qkv_t = w;
    __half *w_out_t = w + 3145728;
    __half *w_ff1_t = w + 4194304;
    __half *w_ff2_t = w + 7340032;

    cudaFuncSetAttribute(gemm_mma<1>, cudaFuncAttributeMaxDynamicSharedMemorySize, GEMM_SMEM);
    cudaFuncSetAttribute(gemm_mma<2>, cudaFuncAttributeMaxDynamicSharedMemorySize, GEMM_SMEM);
    cudaFuncSetAttribute(gemm_mma<3>, cudaFuncAttributeMaxDynamicSharedMemorySize, GEMM_SMEM);
    cudaFuncSetAttribute(attn_mma, cudaFuncAttributeMaxDynamicSharedMemorySize, ATT_SMEM);

    // 0. weight prep (one merged launch)
    prep_all<<<10240, 256>>>(w_qkv, w_out, w_ff1, w_ff2, w);

    // 1. LN1 -> fp16
    ln_half<<<ROWS, 256>>>(x, ln1_g, ln1_b, h);

    // 2. QKV projection -> fp16  (persistent grid)
    gemm_mma<3><<<NPERS, 256, GEMM_SMEM>>>(
        h, w_qkv_t, b_qkv, nullptr, nullptr, qkvh, ROWS, 3 * D_MODEL, D_MODEL);

    // 3. tensor-core attention -> fp16 ctx
    attn_mma<<<dim3(SEQ / 64, NH, BATCH), 256, ATT_SMEM>>>(qkvh, ctx);

    // 4. out-projection + residual -> fp32 x2
    gemm_mma<1><<<NPERS, 256, GEMM_SMEM>>>(
        ctx, w_out_t, b_out, x, x2, nullptr, ROWS, D_MODEL, D_MODEL);

    // 5. LN2 -> fp16
    ln_half<<<ROWS, 256>>>(x2, ln2_g, ln2_b, h);

    // 6. FF1 + gelu -> fp16
    gemm_mma<2><<<NPERS, 256, GEMM_SMEM>>>(
        h, w_ff1_t, b_ff1, nullptr, nullptr, ff, ROWS, D_FF, D_MODEL);

    // 7. FF2 + residual -> output
    gemm_mma<1><<<NPERS, 256, GEMM_SMEM>>>(
        ff, w_ff2_t, b_ff2, x2, out, nullptr, ROWS, D_MODEL, D_FF);
}